// round 2
// baseline (speedup 1.0000x reference)
#include <cuda_runtime.h>
#include <math.h>

#define TT 4096
#define BB 32
#define NH 100
#define NM 65

// ---- scratch (static __device__: no allocations allowed) ----
__device__ float g_tfac[TT*NH];                    // 1 + 0.225*sin(phase_t + off_k)
__device__ __align__(16) float g_nfac[TT*NM];      // 1 + 0.6*sin(ripple_m + phase_t)
__device__ float g_cmean[TT];                      // mean-over-batch centroid
__device__ float g_hmean[TT*NH];                   // mean-over-batch h_mid (pre-resonance)
__device__ float g_sreso[TT];                      // 0.4*sin(clock_t)

__device__ __forceinline__ float wmax(float v){
  #pragma unroll
  for (int d=16; d; d>>=1) v = fmaxf(v, __shfl_xor_sync(0xffffffffu, v, d));
  return v;
}
__device__ __forceinline__ float wsum(float v){
  #pragma unroll
  for (int d=16; d; d>>=1) v += __shfl_xor_sync(0xffffffffu, v, d);
  return v;
}

// ---- K0: per-(t,k) sinusoidal factors -------------------------------------
__global__ void k_factors(){
  int t = blockIdx.x, j = threadIdx.x;
  // ref adds f32(inc) each step and wraps at f32(2pi); closed form in double
  // tracks the f32 trajectory to ~1e-5 rad.
  const double INC  = (double)(float)1.0053096491487339;   // 2pi*40*64/16000 as f32
  const double WRAP = (double)(float)6.283185307179586;    // f32(2pi)
  float phase = (float)fmod((double)(t+1)*INC, WRAP);
  if (j < NH) {
    float off = (float)((double)j * (4.71238898038469/99.0));  // linspace(0, 1.5pi, 100)
    g_tfac[t*NH+j] = 1.0f + 0.225f*sinf(phase + off);
  } else if (j < NH+NM) {
    int m = j - NH;
    float rb = (float)m * 7.853981633974483f;                  // arange*2.5pi (f32)
    g_nfac[t*NM+m] = 1.0f + 0.6f*sinf(rb + phase);
  }
}

// ---- K1: per-t stats: C[t] and mean_b(h_mid) ------------------------------
// one block per t, 8 warps x 4 rows = 32 batch rows
__global__ __launch_bounds__(256) void k_stats(const float* __restrict__ harm){
  int t = blockIdx.x;
  int warp = threadIdx.x>>5, lane = threadIdx.x&31;
  __shared__ float s_tfac[NH];
  __shared__ float s_hsum[NH];
  __shared__ float s_csum;
  if (threadIdx.x < NH){ s_tfac[threadIdx.x]=g_tfac[t*NH+threadIdx.x]; s_hsum[threadIdx.x]=0.f; }
  if (threadIdx.x == 0) s_csum = 0.f;
  __syncthreads();
  bool l4 = lane < 4;
  float f0=s_tfac[lane], f1=s_tfac[lane+32], f2=s_tfac[lane+64], f3=l4?s_tfac[lane+96]:0.f;
  float a0=0,a1=0,a2=0,a3=0, cacc=0;
  #pragma unroll
  for (int r=0;r<4;++r){
    int b = warp + r*8;
    const float* row = harm + ((size_t)b*TT + t)*NH;
    float x0=row[lane], x1=row[lane+32], x2=row[lane+64];
    float x3 = l4 ? row[lane+96] : 0.f;
    float mo = fmaxf(fmaxf(x0,x1),x2); if(l4) mo = fmaxf(mo,x3);
    mo = fmaxf(wmax(mo), 1e-6f);
    float s0=__powf(fmaxf(x0,1e-6f),3.4f);
    float s1=__powf(fmaxf(x1,1e-6f),3.4f);
    float s2=__powf(fmaxf(x2,1e-6f),3.4f);
    float s3=l4?__powf(fmaxf(x3,1e-6f),3.4f):0.f;
    float ml = fmaxf(fmaxf(s0,s1),s2); if(l4) ml = fmaxf(ml,s3);
    float ms = fmaxf(wmax(ml), 1e-6f);
    float ratio = mo/ms;
    float h0=s0*ratio*f0, h1=s1*ratio*f1, h2=s2*ratio*f2, h3=s3*ratio*f3;
    float num = h0*(float)lane + h1*(float)(lane+32) + h2*(float)(lane+64) + h3*(float)(lane+96);
    float den = h0+h1+h2+h3;
    num = wsum(num); den = wsum(den);
    if (lane==0) cacc += num / fmaxf(den, 1e-6f);
    a0+=h0; a1+=h1; a2+=h2; a3+=h3;
  }
  atomicAdd(&s_hsum[lane],    a0);
  atomicAdd(&s_hsum[lane+32], a1);
  atomicAdd(&s_hsum[lane+64], a2);
  if (l4) atomicAdd(&s_hsum[lane+96], a3);
  if (lane==0) atomicAdd(&s_csum, cacc);
  __syncthreads();
  if (threadIdx.x < NH) g_hmean[t*NH+threadIdx.x] = s_hsum[threadIdx.x] * (1.f/32.f);
  if (threadIdx.x == 0) g_cmean[t] = s_csum * (1.f/32.f);
}

// ---- K2: fb affine scan + clock prefix sum + sin(clock) -------------------
// single block, 128 threads x 32 elements
__global__ void k_scan(){
  __shared__ double s_clk[TT];          // 32 KB
  __shared__ double s_wa[4], s_wb[4], s_ws[4];
  int tid = threadIdx.x;
  int lane = tid & 31, warp = tid >> 5;
  int base = tid * 32;
  const double RATE_K = 0.725 * 6.283185307179586 * 0.004;  // (0.25+0.475)*2pi*frame_dur
  // pass 1: local affine composite for fb_t = 0.9 fb + u_t
  double v = 0.0;
  for (int j=0;j<32;++j){
    double u = 0.1*(((double)g_cmean[base+j] - 30.0)/40.0);
    v = 0.9*v + u;
  }
  double a = 0.03433683820292512;  // 0.9^32
  double b = v;
  #pragma unroll
  for (int d=1; d<32; d<<=1){
    double pa = __shfl_up_sync(0xffffffffu, a, d);
    double pb = __shfl_up_sync(0xffffffffu, b, d);
    if (lane >= d){ b = a*pb + b; a = a*pa; }
  }
  if (lane == 31){ s_wa[warp]=a; s_wb[warp]=b; }
  __syncthreads();
  double wpre = 0.0;
  for (int w=0; w<warp; ++w) wpre = s_wa[w]*wpre + s_wb[w];
  double ae = __shfl_up_sync(0xffffffffu, a, 1);
  double be = __shfl_up_sync(0xffffffffu, b, 1);
  double fb = (lane==0) ? wpre : (ae*wpre + be);
  // pass 2: replay, accumulate local rate cumsum
  double csum = 0.0;
  for (int j=0;j<32;++j){
    double u = 0.1*(((double)g_cmean[base+j] - 30.0)/40.0);
    fb = 0.9*fb + u;
    double rate = RATE_K * (1.0 + 0.4*fb);
    csum += rate;
    s_clk[base+j] = csum;
  }
  double S = csum, ss = S;
  #pragma unroll
  for (int d=1; d<32; d<<=1){
    double p = __shfl_up_sync(0xffffffffu, ss, d);
    if (lane >= d) ss += p;
  }
  if (lane == 31) s_ws[warp] = ss;
  __syncthreads();
  double off = 0.0;
  for (int w=0; w<warp; ++w) off += s_ws[w];
  double excl = off + ss - S;
  for (int j=0;j<32;++j){
    double c = fmod(excl + s_clk[base+j], 6.283185307179586);
    g_sreso[base+j] = 0.4f * sinf((float)c);
  }
}

// ---- K3: harmonic output (recompute h_mid, apply resonance + memory) ------
__global__ __launch_bounds__(256) void k_out_h(const float* __restrict__ harm,
                                               float* __restrict__ out){
  int t = blockIdx.x;
  int warp = threadIdx.x>>5, lane = threadIdx.x&31;
  __shared__ float s_tfac[NH];
  __shared__ float s_mem[NH];
  float sr = g_sreso[t];
  if (threadIdx.x < NH){
    s_tfac[threadIdx.x] = g_tfac[t*NH+threadIdx.x];
    float rel = (float)threadIdx.x/99.0f*2.0f - 1.0f;
    float mv = 0.f;
    if (t >= 149){
      float srp = g_sreso[t-149];
      mv = 0.4f * (1.0f + srp*rel) * g_hmean[(t-149)*NH + threadIdx.x];
    }
    s_mem[threadIdx.x] = mv;
  }
  __syncthreads();
  bool l4 = lane < 4;
  float f0=s_tfac[lane], f1=s_tfac[lane+32], f2=s_tfac[lane+64], f3=l4?s_tfac[lane+96]:0.f;
  float m0=s_mem[lane],  m1=s_mem[lane+32],  m2=s_mem[lane+64],  m3=l4?s_mem[lane+96]:0.f;
  float r0=(float)lane/99.0f*2.0f-1.0f;
  float r1=(float)(lane+32)/99.0f*2.0f-1.0f;
  float r2=(float)(lane+64)/99.0f*2.0f-1.0f;
  float r3=(float)(lane+96)/99.0f*2.0f-1.0f;
  float q0=1.0f+sr*r0, q1=1.0f+sr*r1, q2=1.0f+sr*r2, q3=1.0f+sr*r3;
  float scale = (t==0) ? 1.0f : 0.6f;   // t==0 passes through; mem term is 0 there
  #pragma unroll
  for (int r=0;r<4;++r){
    int bb = warp + r*8;
    const float* row  = harm + ((size_t)bb*TT + t)*NH;
    float*       orow = out  + ((size_t)bb*TT + t)*NH;
    float x0=row[lane], x1=row[lane+32], x2=row[lane+64];
    float x3 = l4 ? row[lane+96] : 0.f;
    float mo = fmaxf(fmaxf(x0,x1),x2); if(l4) mo = fmaxf(mo,x3);
    mo = fmaxf(wmax(mo), 1e-6f);
    float s0=__powf(fmaxf(x0,1e-6f),3.4f);
    float s1=__powf(fmaxf(x1,1e-6f),3.4f);
    float s2=__powf(fmaxf(x2,1e-6f),3.4f);
    float s3=l4?__powf(fmaxf(x3,1e-6f),3.4f):0.f;
    float ml = fmaxf(fmaxf(s0,s1),s2); if(l4) ml = fmaxf(ml,s3);
    float ms = fmaxf(wmax(ml), 1e-6f);
    float ratio = mo/ms;
    orow[lane]    = scale*s0*ratio*f0*q0 + m0;
    orow[lane+32] = scale*s1*ratio*f1*q1 + m1;
    orow[lane+64] = scale*s2*ratio*f2*q2 + m2;
    if (l4) orow[lane+96] = scale*s3*ratio*f3*q3 + m3;
  }
}

// ---- K4: noise output, fully elementwise, float4 --------------------------
__global__ void k_noise(const float4* __restrict__ nin, float4* __restrict__ nout){
  int i = blockIdx.x*blockDim.x + threadIdx.x;
  const int NV = BB*TT*NM/4;
  if (i >= NV) return;
  int fi = (i*4) % (TT*NM);   // per-(t,m) factor index; divisible by 4
  float4 v = nin[i];
  float4 f = *reinterpret_cast<const float4*>(&g_nfac[fi]);
  v.x *= f.x; v.y *= f.y; v.z *= f.z; v.w *= f.w;
  nout[i] = v;
}

extern "C" void kernel_launch(void* const* d_in, const int* in_sizes, int n_in,
                              void* d_out, int out_size){
  const float* harm  = (const float*)d_in[0];
  const float* noise = (const float*)d_in[1];
  float* outh = (float*)d_out;
  float* outn = outh + (size_t)BB*TT*NH;   // h_out [32,4096,100] then n_out [32,4096,65]
  k_factors<<<TT, 192>>>();
  k_stats  <<<TT, 256>>>(harm);
  k_scan   <<<1, 128>>>();
  k_out_h  <<<TT, 256>>>(harm, outh);
  const int NV = BB*TT*NM/4;
  k_noise  <<<(NV + 255)/256, 256>>>((const float4*)noise, (float4*)outn);
}

// round 5
// speedup vs baseline: 1.0439x; 1.0439x over previous
#include <cuda_runtime.h>
#include <math.h>

#define TT 4096
#define BB 32
#define NH 100
#define NM 65

// ---- scratch (__device__ globals: allocations forbidden) ----
__device__ __align__(16) float g_tfac[TT*NH];      // 1 + 0.225*sin(phase_t + off_k)
__device__ __align__(16) float g_nfac[TT*NM];      // 1 + 0.6*sin(ripple_m + phase_t)
__device__ __align__(16) float g_hmid[(size_t)BB*TT*NH];  // 52.4MB: h after tension+turbulence
__device__ __align__(16) float g_a[TT*NH];         // scale*(1+sr_t*rel_k)
__device__ __align__(16) float g_c[TT*NH];         // memory additive term
__device__ float g_cmean[TT];                      // batch-mean centroid
__device__ float g_hmean[TT*NH];                   // batch-mean h_mid
__device__ float g_sreso[TT];                      // 0.4*sin(clock_t)

__device__ __forceinline__ float wmax(float v){
  #pragma unroll
  for (int d=16; d; d>>=1) v = fmaxf(v, __shfl_xor_sync(0xffffffffu, v, d));
  return v;
}
__device__ __forceinline__ float wsum(float v){
  #pragma unroll
  for (int d=16; d; d>>=1) v += __shfl_xor_sync(0xffffffffu, v, d);
  return v;
}

// ---- K0: per-(t,k) sinusoidal factors -------------------------------------
__global__ void k_factors(){
  int t = blockIdx.x, j = threadIdx.x;
  // ref adds f32(inc) each step and wraps at f32(2pi); double closed form
  // tracks the f32 trajectory to ~1e-5 rad.
  const double INC  = (double)(float)1.0053096491487339;   // 2pi*40*64/16000 as f32
  const double WRAP = (double)(float)6.283185307179586;    // f32(2pi)
  float phase = (float)fmod((double)(t+1)*INC, WRAP);
  if (j < NH) {
    float off = (float)((double)j * (4.71238898038469/99.0));  // linspace(0,1.5pi,100)
    g_tfac[t*NH+j] = 1.0f + 0.225f*sinf(phase + off);
  } else if (j < NH+NM) {
    int m = j - NH;
    float rb = (float)m * 7.853981633974483f;                  // arange*2.5pi (f32)
    g_nfac[t*NM+m] = 1.0f + 0.6f*sinf(rb + phase);
  }
}

// ---- K1: compute h_mid (tension+turbulence), store it, reduce stats -------
// one block per t; 8 warps x 4 rows; 25 active lanes x float4 per 100-elem row
__global__ __launch_bounds__(256) void k_stats(const float* __restrict__ harm){
  int t = blockIdx.x;
  int warp = threadIdx.x>>5, lane = threadIdx.x&31;
  __shared__ float4 s_tfac[25];
  __shared__ float  s_hsum[NH];
  __shared__ float  s_csum;
  if (threadIdx.x < 25) s_tfac[threadIdx.x] =
      reinterpret_cast<const float4*>(g_tfac + t*NH)[threadIdx.x];
  if (threadIdx.x < NH) s_hsum[threadIdx.x] = 0.f;
  if (threadIdx.x == 0) s_csum = 0.f;
  __syncthreads();
  bool act = lane < 25;
  float4 f = act ? s_tfac[lane] : make_float4(0.f,0.f,0.f,0.f);
  float4 acc = make_float4(0.f,0.f,0.f,0.f);
  float cacc = 0.f;
  float k0 = (float)(lane*4);
  #pragma unroll
  for (int r=0;r<4;++r){
    int b = warp*4 + r;
    size_t rowoff = ((size_t)b*TT + t)*NH;
    float4 x = act ? reinterpret_cast<const float4*>(harm + rowoff)[lane]
                   : make_float4(0.f,0.f,0.f,0.f);
    float mo = fmaxf(fmaxf(x.x,x.y), fmaxf(x.z,x.w));
    mo = fmaxf(wmax(mo), 1e-6f);
    float4 s;
    s.x = __powf(fmaxf(x.x,1e-6f), 3.4f);
    s.y = __powf(fmaxf(x.y,1e-6f), 3.4f);
    s.z = __powf(fmaxf(x.z,1e-6f), 3.4f);
    s.w = __powf(fmaxf(x.w,1e-6f), 3.4f);
    float ml = act ? fmaxf(fmaxf(s.x,s.y), fmaxf(s.z,s.w)) : 0.f;
    float ms = fmaxf(wmax(ml), 1e-6f);
    float ratio = mo/ms;
    float4 h;
    h.x = s.x*ratio*f.x; h.y = s.y*ratio*f.y;
    h.z = s.z*ratio*f.z; h.w = s.w*ratio*f.w;
    float num = h.x*k0 + h.y*(k0+1.f) + h.z*(k0+2.f) + h.w*(k0+3.f);
    float den = h.x+h.y+h.z+h.w;
    num = wsum(num); den = wsum(den);
    if (lane==0) cacc += num / fmaxf(den, 1e-6f);
    if (act) reinterpret_cast<float4*>(g_hmid + rowoff)[lane] = h;
    acc.x+=h.x; acc.y+=h.y; acc.z+=h.z; acc.w+=h.w;
  }
  if (act){
    atomicAdd(&s_hsum[lane*4+0], acc.x);
    atomicAdd(&s_hsum[lane*4+1], acc.y);
    atomicAdd(&s_hsum[lane*4+2], acc.z);
    atomicAdd(&s_hsum[lane*4+3], acc.w);
  }
  if (lane==0) atomicAdd(&s_csum, cacc);
  __syncthreads();
  if (threadIdx.x < NH) g_hmean[t*NH+threadIdx.x] = s_hsum[threadIdx.x] * (1.f/32.f);
  if (threadIdx.x == 0) g_cmean[t] = s_csum * (1.f/32.f);
}

// ---- K2: fb affine scan + clock prefix sum + sin(clock) (double prec) -----
__global__ void k_scan(){
  __shared__ double s_clk[TT];
  __shared__ double s_wa[4], s_wb[4], s_ws[4];
  int tid = threadIdx.x;
  int lane = tid & 31, warp = tid >> 5;
  int base = tid * 32;
  const double RATE_K = 0.725 * 6.283185307179586 * 0.004;
  double v = 0.0;
  for (int j=0;j<32;++j){
    double u = 0.1*(((double)g_cmean[base+j] - 30.0)/40.0);
    v = 0.9*v + u;
  }
  double a = 0.03433683820292512;  // 0.9^32
  double b = v;
  #pragma unroll
  for (int d=1; d<32; d<<=1){
    double pa = __shfl_up_sync(0xffffffffu, a, d);
    double pb = __shfl_up_sync(0xffffffffu, b, d);
    if (lane >= d){ b = a*pb + b; a = a*pa; }
  }
  if (lane == 31){ s_wa[warp]=a; s_wb[warp]=b; }
  __syncthreads();
  double wpre = 0.0;
  for (int w=0; w<warp; ++w) wpre = s_wa[w]*wpre + s_wb[w];
  double ae = __shfl_up_sync(0xffffffffu, a, 1);
  double be = __shfl_up_sync(0xffffffffu, b, 1);
  double fb = (lane==0) ? wpre : (ae*wpre + be);
  double csum = 0.0;
  for (int j=0;j<32;++j){
    double u = 0.1*(((double)g_cmean[base+j] - 30.0)/40.0);
    fb = 0.9*fb + u;
    csum += RATE_K * (1.0 + 0.4*fb);
    s_clk[base+j] = csum;
  }
  double S = csum, ss = S;
  #pragma unroll
  for (int d=1; d<32; d<<=1){
    double p = __shfl_up_sync(0xffffffffu, ss, d);
    if (lane >= d) ss += p;
  }
  if (lane == 31) s_ws[warp] = ss;
  __syncthreads();
  double off = 0.0;
  for (int w=0; w<warp; ++w) off += s_ws[w];
  double excl = off + ss - S;
  for (int j=0;j<32;++j){
    double c = fmod(excl + s_clk[base+j], 6.283185307179586);
    g_sreso[base+j] = 0.4f * sinf((float)c);
  }
}

// ---- K3: build per-(t,k) affine tables a,c --------------------------------
__global__ void k_combine(){
  int t = blockIdx.x, k = threadIdx.x;
  if (k >= NH) return;
  float sr = g_sreso[t];
  float rel = (float)k/99.0f*2.0f - 1.0f;
  float q = 1.0f + sr*rel;
  float a, c;
  if (t == 0){ a = q; c = 0.f; }                       // first frame passes through
  else if (t < 149){ a = 0.6f*q; c = 0.f; }            // delay slot still zero
  else {
    a = 0.6f*q;
    float srp = g_sreso[t-149];
    c = 0.4f * (1.0f + srp*rel) * g_hmean[(t-149)*NH + k];
  }
  g_a[t*NH+k] = a;
  g_c[t*NH+k] = c;
}

// ---- K4: fused streaming epilogue: h = a*h_mid + c ; n = noise*nfac -------
__global__ __launch_bounds__(256) void k_out(const float4* __restrict__ nin,
                                             float4* __restrict__ outh,
                                             float4* __restrict__ outn){
  const int NVH = BB*TT*NH/4;      // 3,276,800
  const int NVN = BB*TT*NM/4;      // 2,129,920
  int i = blockIdx.x*blockDim.x + threadIdx.x;
  if (i < NVH){
    int tk = i % (TT*NH/4);
    float4 v = reinterpret_cast<const float4*>(g_hmid)[i];
    float4 a = reinterpret_cast<const float4*>(g_a)[tk];
    float4 c = reinterpret_cast<const float4*>(g_c)[tk];
    float4 o;
    o.x = fmaf(a.x, v.x, c.x); o.y = fmaf(a.y, v.y, c.y);
    o.z = fmaf(a.z, v.z, c.z); o.w = fmaf(a.w, v.w, c.w);
    outh[i] = o;
  } else if (i < NVH + NVN){
    int j = i - NVH;
    int fi = j % (TT*NM/4);
    float4 v = nin[j];
    float4 f = reinterpret_cast<const float4*>(g_nfac)[fi];
    v.x *= f.x; v.y *= f.y; v.z *= f.z; v.w *= f.w;
    outn[j] = v;
  }
}

extern "C" void kernel_launch(void* const* d_in, const int* in_sizes, int n_in,
                              void* d_out, int out_size){
  const float* harm  = (const float*)d_in[0];
  const float* noise = (const float*)d_in[1];
  float* outh = (float*)d_out;
  float* outn = outh + (size_t)BB*TT*NH;
  k_factors<<<TT, 192>>>();
  k_stats  <<<TT, 256>>>(harm);
  k_scan   <<<1, 128>>>();
  k_combine<<<TT, 128>>>();
  const int NV = BB*TT*(NH+NM)/4;
  k_out    <<<(NV + 255)/256, 256>>>((const float4*)noise, (float4*)outh, (float4*)outn);
}